// round 7
// baseline (speedup 1.0000x reference)
#include <cuda_runtime.h>

#define TOTD 512
#define HIDD 256
#define OUTD 128

// Scratch: per-(k,quarter) partial sum-of-squares and partial product.
__device__ float g_sum[1024];
__device__ float g_prod[1024];

__global__ void __launch_bounds__(128, 8) wavelet_main_kernel(
    const float* __restrict__ h, const float* __restrict__ y, const float* __restrict__ u,
    const float* __restrict__ W1, const float* __restrict__ b1,
    const float* __restrict__ W2, const float* __restrict__ b2,
    const float* __restrict__ Wy, const float* __restrict__ by,
    float* __restrict__ out)
{
    __shared__ float4 s_inp[TOTD / 4];
    // Per-warp deferred partials: [4 warps][32 rows][33 lanes-padded]
    __shared__ float s_part[4][32][33];

    const int tid = threadIdx.x;
    // Build inp = concat(h[256], y[128], u[128]) in shared.
    float* si = (float*)s_inp;
    for (int i = tid; i < TOTD; i += 128) {
        float v;
        if (i < HIDD)             v = h[i];
        else if (i < HIDD + OUTD) v = y[i - HIDD];
        else                      v = u[i - HIDD - OUTD];
        si[i] = v;
    }
    __syncthreads();

    const int lane = tid & 31;
    const int w    = tid >> 5;   // warp id 0..3
    const int bx   = blockIdx.x;

    // Input slice for this lane, register-resident (reused across all rows).
    const float4 iv0 = s_inp[lane +  0];
    const float4 iv1 = s_inp[lane + 32];
    const float4 iv2 = s_inp[lane + 64];
    const float4 iv3 = s_inp[lane + 96];

    if (bx < 1024) {
        // Hidden-unit matvecs: block bx handles k = bx/4, rows [(bx&3)*128, +128).
        // Each of 4 warps owns 32 consecutive rows.
        const int kk = bx >> 2;      // 0..255
        const int q  = bx & 3;
        const float* W;
        const float* b;
        if (kk == 0) { W = W1; b = b1; }
        else {
            W = W2 + (size_t)(kk - 1) * TOTD * TOTD;
            b = b2 + (size_t)(kk - 1) * TOTD;
        }
        const int rbase = q * 128 + w * 32;

        // Pure streaming loop: 8 LDG.128 + 64 FFMA + 2 STS per iteration.
        // All 8 loads issue before first consumption (MLP=8/warp); no
        // reductions, no biases, no shuffles inside the loop.
        #pragma unroll 1
        for (int i = 0; i < 16; i++) {
            const int rowA = rbase + 2 * i;
            const float4* WrA = (const float4*)(W + (size_t)rowA * TOTD);
            const float4* WrB = WrA + (TOTD / 4);
            float4 a0 = __ldcs(WrA + lane +  0);
            float4 a1 = __ldcs(WrA + lane + 32);
            float4 a2 = __ldcs(WrA + lane + 64);
            float4 a3 = __ldcs(WrA + lane + 96);
            float4 c0 = __ldcs(WrB + lane +  0);
            float4 c1 = __ldcs(WrB + lane + 32);
            float4 c2 = __ldcs(WrB + lane + 64);
            float4 c3 = __ldcs(WrB + lane + 96);

            // Tree-structured dots to keep dependency depth low.
            float tA0 = a0.x*iv0.x + a0.y*iv0.y + a0.z*iv0.z + a0.w*iv0.w;
            float tA1 = a1.x*iv1.x + a1.y*iv1.y + a1.z*iv1.z + a1.w*iv1.w;
            float tA2 = a2.x*iv2.x + a2.y*iv2.y + a2.z*iv2.z + a2.w*iv2.w;
            float tA3 = a3.x*iv3.x + a3.y*iv3.y + a3.z*iv3.z + a3.w*iv3.w;
            s_part[w][2 * i + 0][lane] = (tA0 + tA1) + (tA2 + tA3);

            float tB0 = c0.x*iv0.x + c0.y*iv0.y + c0.z*iv0.z + c0.w*iv0.w;
            float tB1 = c1.x*iv1.x + c1.y*iv1.y + c1.z*iv1.z + c1.w*iv1.w;
            float tB2 = c2.x*iv2.x + c2.y*iv2.y + c2.z*iv2.z + c2.w*iv2.w;
            float tB3 = c3.x*iv3.x + c3.y*iv3.y + c3.z*iv3.z + c3.w*iv3.w;
            s_part[w][2 * i + 1][lane] = (tB0 + tB1) + (tB2 + tB3);
        }
        __syncwarp();

        // Epilogue: lane l reduces row (rbase + l): 32 conflict-free LDS + bias.
        float acc = 0.0f;
        #pragma unroll
        for (int j = 0; j < 32; j++) acc += s_part[w][lane][j];
        const float hv = acc + b[rbase + lane];
        const float x2 = hv * hv;
        float runs = x2;
        float runp = 1.0f - x2;
        #pragma unroll
        for (int o = 16; o > 0; o >>= 1) {
            runs += __shfl_xor_sync(0xffffffffu, runs, o);
            runp *= __shfl_xor_sync(0xffffffffu, runp, o);
        }
        // Per-warp partials: 4 warps per block, combined by the tail kernel.
        if (lane == 0) {
            // index: [k(8bits) | quarter(2) ] -> we store per (bx, w) into a
            // flat [1024] array by pre-reducing the 4 warps via shared.
            s_part[0][0][36 + w * 2]     = runs;   // reuse smem (safe: all warps past reads)
            s_part[0][0][36 + w * 2 + 1] = runp;
        }
        __syncthreads();
        if (tid == 0) {
            float s = 0.0f, p = 1.0f;
            #pragma unroll
            for (int i = 0; i < 4; i++) {
                s += s_part[0][0][36 + i * 2];
                p *= s_part[0][0][36 + i * 2 + 1];
            }
            g_sum[bx]  = s;
            g_prod[bx] = p;
        }
    } else {
        // y_out blocks: bx in [1024, 1028), 32 rows of Wy each, 8 rows per warp.
        const int rb = (bx - 1024) * 32 + w * 8;
        #pragma unroll
        for (int i = 0; i < 8; i += 2) {
            const int rowA = rb + i;
            const float4* WrA = (const float4*)(Wy + (size_t)rowA * TOTD);
            const float4* WrB = WrA + (TOTD / 4);
            float4 a0 = __ldg(WrA + lane +  0);
            float4 a1 = __ldg(WrA + lane + 32);
            float4 a2 = __ldg(WrA + lane + 64);
            float4 a3 = __ldg(WrA + lane + 96);
            float4 c0 = __ldg(WrB + lane +  0);
            float4 c1 = __ldg(WrB + lane + 32);
            float4 c2 = __ldg(WrB + lane + 64);
            float4 c3 = __ldg(WrB + lane + 96);

            float accA = a0.x*iv0.x + a0.y*iv0.y + a0.z*iv0.z + a0.w*iv0.w;
            float accB = c0.x*iv0.x + c0.y*iv0.y + c0.z*iv0.z + c0.w*iv0.w;
            accA      += a1.x*iv1.x + a1.y*iv1.y + a1.z*iv1.z + a1.w*iv1.w;
            accB      += c1.x*iv1.x + c1.y*iv1.y + c1.z*iv1.z + c1.w*iv1.w;
            accA      += a2.x*iv2.x + a2.y*iv2.y + a2.z*iv2.z + a2.w*iv2.w;
            accB      += c2.x*iv2.x + c2.y*iv2.y + c2.z*iv2.z + c2.w*iv2.w;
            accA      += a3.x*iv3.x + a3.y*iv3.y + a3.z*iv3.z + a3.w*iv3.w;
            accB      += c3.x*iv3.x + c3.y*iv3.y + c3.z*iv3.z + c3.w*iv3.w;

            #pragma unroll
            for (int o = 16; o > 0; o >>= 1) {
                accA += __shfl_xor_sync(0xffffffffu, accA, o);
                accB += __shfl_xor_sync(0xffffffffu, accB, o);
            }
            if (lane == 0) {
                out[HIDD + rowA]     = accA + by[rowA];
                out[HIDD + rowA + 1] = accB + by[rowA + 1];
            }
        }
    }
}

__global__ void wavelet_combine_kernel(float* __restrict__ out)
{
    const int t = threadIdx.x;   // 0..255
    const float s = (g_sum[4 * t + 0] + g_sum[4 * t + 1])
                  + (g_sum[4 * t + 2] + g_sum[4 * t + 3]);
    float a;
    if (t == 0) {
        a = expf(-0.5f * s);   // Gaussian scaling unit
    } else {
        const float p = (g_prod[4 * t + 0] * g_prod[4 * t + 1])
                      * (g_prod[4 * t + 2] * g_prod[4 * t + 3]);
        a = p * expf(-0.5f * s);   // Mexican-hat product
    }
    out[t] = a;
}

extern "C" void kernel_launch(void* const* d_in, const int* in_sizes, int n_in,
                              void* d_out, int out_size)
{
    const float* h  = (const float*)d_in[0];
    const float* y  = (const float*)d_in[1];
    const float* u  = (const float*)d_in[2];
    const float* W1 = (const float*)d_in[3];
    const float* b1 = (const float*)d_in[4];
    const float* W2 = (const float*)d_in[5];
    const float* b2 = (const float*)d_in[6];
    const float* Wy = (const float*)d_in[7];
    const float* by = (const float*)d_in[8];
    float* out = (float*)d_out;

    wavelet_main_kernel<<<1028, 128>>>(h, y, u, W1, b1, W2, b2, Wy, by, out);
    wavelet_combine_kernel<<<1, 256>>>(out);
}

// round 9
// speedup vs baseline: 1.0316x; 1.0316x over previous
#include <cuda_runtime.h>
#include <cooperative_groups.h>

namespace cg = cooperative_groups;

#define TOTD 512
#define HIDD 256
#define OUTD 128

__global__ void __launch_bounds__(128, 8) __cluster_dims__(4, 1, 1)
wavelet_cluster_kernel(
    const float* __restrict__ h, const float* __restrict__ y, const float* __restrict__ u,
    const float* __restrict__ W1, const float* __restrict__ b1,
    const float* __restrict__ W2, const float* __restrict__ b2,
    const float* __restrict__ Wy, const float* __restrict__ by,
    float* __restrict__ out)
{
    __shared__ float4 s_inp[TOTD / 4];
    // Per-warp deferred partials: [4 warps][32 rows][33 lanes-padded]
    __shared__ float s_part[4][32][33];
    __shared__ float s_rs[4], s_rp[4];   // per-warp (sum, prod) partials
    __shared__ float s_cl[8];            // cluster combine slots: [rank*2 + {0,1}]

    cg::cluster_group cluster = cg::this_cluster();
    const unsigned rank = cluster.block_rank();   // == bx & 3

    const int tid = threadIdx.x;
    // Build inp = concat(h[256], y[128], u[128]) in shared: 1 float4 per thread.
    {
        float4 v;
        if (tid < 64)       v = ((const float4*)h)[tid];
        else if (tid < 96)  v = ((const float4*)y)[tid - 64];
        else                v = ((const float4*)u)[tid - 96];
        s_inp[tid] = v;
    }
    __syncthreads();

    const int lane = tid & 31;
    const int w    = tid >> 5;   // warp id 0..3
    const int bx   = blockIdx.x;

    // Input slice for this lane, register-resident (reused across all rows).
    const float4 iv0 = s_inp[lane +  0];
    const float4 iv1 = s_inp[lane + 32];
    const float4 iv2 = s_inp[lane + 64];
    const float4 iv3 = s_inp[lane + 96];

    if (bx < 1024) {
        // Hidden-unit matvecs: block bx handles k = bx/4, rows [rank*128, +128).
        // Each of 4 warps owns 32 consecutive rows.
        const int kk = bx >> 2;      // 0..255
        const float* W;
        const float* b;
        if (kk == 0) { W = W1; b = b1; }
        else {
            W = W2 + (size_t)(kk - 1) * TOTD * TOTD;
            b = b2 + (size_t)(kk - 1) * TOTD;
        }
        const int rbase = (int)rank * 128 + w * 32;

        // Pure streaming loop: 8 LDG.128 + 64 FFMA + 2 STS per iteration.
        // All 8 loads issue before first consumption (MLP=8/warp); no
        // reductions, no biases, no shuffles inside the loop.
        #pragma unroll 1
        for (int i = 0; i < 16; i++) {
            const int rowA = rbase + 2 * i;
            const float4* WrA = (const float4*)(W + (size_t)rowA * TOTD);
            const float4* WrB = WrA + (TOTD / 4);
            float4 a0 = __ldcs(WrA + lane +  0);
            float4 a1 = __ldcs(WrA + lane + 32);
            float4 a2 = __ldcs(WrA + lane + 64);
            float4 a3 = __ldcs(WrA + lane + 96);
            float4 c0 = __ldcs(WrB + lane +  0);
            float4 c1 = __ldcs(WrB + lane + 32);
            float4 c2 = __ldcs(WrB + lane + 64);
            float4 c3 = __ldcs(WrB + lane + 96);

            // Tree-structured dots to keep dependency depth low.
            float tA0 = a0.x*iv0.x + a0.y*iv0.y + a0.z*iv0.z + a0.w*iv0.w;
            float tA1 = a1.x*iv1.x + a1.y*iv1.y + a1.z*iv1.z + a1.w*iv1.w;
            float tA2 = a2.x*iv2.x + a2.y*iv2.y + a2.z*iv2.z + a2.w*iv2.w;
            float tA3 = a3.x*iv3.x + a3.y*iv3.y + a3.z*iv3.z + a3.w*iv3.w;
            s_part[w][2 * i + 0][lane] = (tA0 + tA1) + (tA2 + tA3);

            float tB0 = c0.x*iv0.x + c0.y*iv0.y + c0.z*iv0.z + c0.w*iv0.w;
            float tB1 = c1.x*iv1.x + c1.y*iv1.y + c1.z*iv1.z + c1.w*iv1.w;
            float tB2 = c2.x*iv2.x + c2.y*iv2.y + c2.z*iv2.z + c2.w*iv2.w;
            float tB3 = c3.x*iv3.x + c3.y*iv3.y + c3.z*iv3.z + c3.w*iv3.w;
            s_part[w][2 * i + 1][lane] = (tB0 + tB1) + (tB2 + tB3);
        }
        __syncwarp();

        // Epilogue: lane l reduces row (rbase + l): 32 conflict-free LDS + bias.
        float acc = 0.0f;
        #pragma unroll
        for (int j = 0; j < 32; j++) acc += s_part[w][lane][j];
        const float hv = acc + b[rbase + lane];
        const float x2 = hv * hv;
        float runs = x2;
        float runp = 1.0f - x2;
        #pragma unroll
        for (int o = 16; o > 0; o >>= 1) {
            runs += __shfl_xor_sync(0xffffffffu, runs, o);
            runp *= __shfl_xor_sync(0xffffffffu, runp, o);
        }
        if (lane == 0) { s_rs[w] = runs; s_rp[w] = runp; }
        __syncthreads();

        // CTA partial -> cluster rank 0's smem slot for this rank.
        if (tid == 0) {
            float s = (s_rs[0] + s_rs[1]) + (s_rs[2] + s_rs[3]);
            float p = (s_rp[0] * s_rp[1]) * (s_rp[2] * s_rp[3]);
            float* dst = cluster.map_shared_rank(s_cl, 0);
            dst[rank * 2 + 0] = s;
            dst[rank * 2 + 1] = p;
        }
    } else {
        // y_out blocks: bx in [1024, 1028), 32 rows of Wy each, 8 rows per warp.
        const int rb = (bx - 1024) * 32 + w * 8;
        #pragma unroll
        for (int i = 0; i < 8; i += 2) {
            const int rowA = rb + i;
            const float4* WrA = (const float4*)(Wy + (size_t)rowA * TOTD);
            const float4* WrB = WrA + (TOTD / 4);
            float4 a0 = __ldg(WrA + lane +  0);
            float4 a1 = __ldg(WrA + lane + 32);
            float4 a2 = __ldg(WrA + lane + 64);
            float4 a3 = __ldg(WrA + lane + 96);
            float4 c0 = __ldg(WrB + lane +  0);
            float4 c1 = __ldg(WrB + lane + 32);
            float4 c2 = __ldg(WrB + lane + 64);
            float4 c3 = __ldg(WrB + lane + 96);

            float accA = a0.x*iv0.x + a0.y*iv0.y + a0.z*iv0.z + a0.w*iv0.w;
            float accB = c0.x*iv0.x + c0.y*iv0.y + c0.z*iv0.z + c0.w*iv0.w;
            accA      += a1.x*iv1.x + a1.y*iv1.y + a1.z*iv1.z + a1.w*iv1.w;
            accB      += c1.x*iv1.x + c1.y*iv1.y + c1.z*iv1.z + c1.w*iv1.w;
            accA      += a2.x*iv2.x + a2.y*iv2.y + a2.z*iv2.z + a2.w*iv2.w;
            accB      += c2.x*iv2.x + c2.y*iv2.y + c2.z*iv2.z + c2.w*iv2.w;
            accA      += a3.x*iv3.x + a3.y*iv3.y + a3.z*iv3.z + a3.w*iv3.w;
            accB      += c3.x*iv3.x + c3.y*iv3.y + c3.z*iv3.z + c3.w*iv3.w;

            #pragma unroll
            for (int o = 16; o > 0; o >>= 1) {
                accA += __shfl_xor_sync(0xffffffffu, accA, o);
                accB += __shfl_xor_sync(0xffffffffu, accB, o);
            }
            if (lane == 0) {
                out[HIDD + rowA]     = accA + by[rowA];
                out[HIDD + rowA + 1] = accB + by[rowA + 1];
            }
        }
    }

    // All CTAs of every cluster (incl. the y cluster) arrive here.
    cluster.sync();

    // Rank 0 of each hidden cluster combines the 4 quarter-partials -> out[kk].
    if (bx < 1024 && rank == 0 && tid == 0) {
        const int kk = bx >> 2;
        const float s = (s_cl[0] + s_cl[2]) + (s_cl[4] + s_cl[6]);
        float a;
        if (kk == 0) {
            a = expf(-0.5f * s);   // Gaussian scaling unit
        } else {
            const float p = (s_cl[1] * s_cl[3]) * (s_cl[5] * s_cl[7]);
            a = p * expf(-0.5f * s);   // Mexican-hat product
        }
        out[kk] = a;
    }
}

extern "C" void kernel_launch(void* const* d_in, const int* in_sizes, int n_in,
                              void* d_out, int out_size)
{
    const float* h  = (const float*)d_in[0];
    const float* y  = (const float*)d_in[1];
    const float* u  = (const float*)d_in[2];
    const float* W1 = (const float*)d_in[3];
    const float* b1 = (const float*)d_in[4];
    const float* W2 = (const float*)d_in[5];
    const float* b2 = (const float*)d_in[6];
    const float* Wy = (const float*)d_in[7];
    const float* by = (const float*)d_in[8];
    float* out = (float*)d_out;

    wavelet_cluster_kernel<<<1028, 128>>>(h, y, u, W1, b1, W2, b2, Wy, by, out);
}

// round 10
// speedup vs baseline: 1.0406x; 1.0088x over previous
#include <cuda_runtime.h>
#include <cooperative_groups.h>

namespace cg = cooperative_groups;

#define TOTD 512
#define HIDD 256
#define OUTD 128

__global__ void __launch_bounds__(128, 4) __cluster_dims__(4, 1, 1)
wavelet_cluster_kernel(
    const float* __restrict__ h, const float* __restrict__ y, const float* __restrict__ u,
    const float* __restrict__ W1, const float* __restrict__ b1,
    const float* __restrict__ W2, const float* __restrict__ b2,
    const float* __restrict__ Wy, const float* __restrict__ by,
    float* __restrict__ out)
{
    __shared__ float4 s_inp[TOTD / 4];
    // Per-warp deferred partials: [4 warps][32 rows][33 lanes-padded]
    __shared__ float s_part[4][32][33];
    __shared__ float s_rs[4], s_rp[4];   // per-warp (sum, prod) partials
    __shared__ float s_cl[8];            // cluster combine slots: [rank*2 + {0,1}]

    cg::cluster_group cluster = cg::this_cluster();
    const unsigned rank = cluster.block_rank();   // == bx & 3

    const int tid = threadIdx.x;
    // Build inp = concat(h[256], y[128], u[128]) in shared: 1 float4 per thread.
    {
        float4 v;
        if (tid < 64)       v = ((const float4*)h)[tid];
        else if (tid < 96)  v = ((const float4*)y)[tid - 64];
        else                v = ((const float4*)u)[tid - 96];
        s_inp[tid] = v;
    }
    __syncthreads();

    const int lane = tid & 31;
    const int w    = tid >> 5;   // warp id 0..3
    const int bx   = blockIdx.x;

    // Input slice for this lane, register-resident (reused across all rows).
    const float4 iv0 = s_inp[lane +  0];
    const float4 iv1 = s_inp[lane + 32];
    const float4 iv2 = s_inp[lane + 64];
    const float4 iv3 = s_inp[lane + 96];

    if (bx < 1024) {
        // Hidden-unit matvecs: block bx handles k = bx/4, rows [rank*128, +128).
        // Each of 4 warps owns 32 consecutive rows.
        const int kk = bx >> 2;      // 0..255
        const float* W;
        const float* b;
        if (kk == 0) { W = W1; b = b1; }
        else {
            W = W2 + (size_t)(kk - 1) * TOTD * TOTD;
            b = b2 + (size_t)(kk - 1) * TOTD;
        }
        const int rbase = (int)rank * 128 + w * 32;

        // Streaming loop: 4 rows per iteration -> 16 LDG.128 (2 KB) in flight
        // per warp before first consumption. No reductions/biases/shuffles
        // inside the loop; partials deferred to smem.
        #pragma unroll 1
        for (int i = 0; i < 8; i++) {
            const float4* R0 = (const float4*)(W + (size_t)(rbase + 4 * i) * TOTD);
            const float4* R1 = R0 + 128;
            const float4* R2 = R0 + 256;
            const float4* R3 = R0 + 384;
            float4 a0 = __ldcs(R0 + lane +  0);
            float4 a1 = __ldcs(R0 + lane + 32);
            float4 a2 = __ldcs(R0 + lane + 64);
            float4 a3 = __ldcs(R0 + lane + 96);
            float4 c0 = __ldcs(R1 + lane +  0);
            float4 c1 = __ldcs(R1 + lane + 32);
            float4 c2 = __ldcs(R1 + lane + 64);
            float4 c3 = __ldcs(R1 + lane + 96);
            float4 d0 = __ldcs(R2 + lane +  0);
            float4 d1 = __ldcs(R2 + lane + 32);
            float4 d2 = __ldcs(R2 + lane + 64);
            float4 d3 = __ldcs(R2 + lane + 96);
            float4 e0 = __ldcs(R3 + lane +  0);
            float4 e1 = __ldcs(R3 + lane + 32);
            float4 e2 = __ldcs(R3 + lane + 64);
            float4 e3 = __ldcs(R3 + lane + 96);

            // Tree-structured dots, one partial per row.
            float tA0 = a0.x*iv0.x + a0.y*iv0.y + a0.z*iv0.z + a0.w*iv0.w;
            float tA1 = a1.x*iv1.x + a1.y*iv1.y + a1.z*iv1.z + a1.w*iv1.w;
            float tA2 = a2.x*iv2.x + a2.y*iv2.y + a2.z*iv2.z + a2.w*iv2.w;
            float tA3 = a3.x*iv3.x + a3.y*iv3.y + a3.z*iv3.z + a3.w*iv3.w;
            s_part[w][4 * i + 0][lane] = (tA0 + tA1) + (tA2 + tA3);

            float tB0 = c0.x*iv0.x + c0.y*iv0.y + c0.z*iv0.z + c0.w*iv0.w;
            float tB1 = c1.x*iv1.x + c1.y*iv1.y + c1.z*iv1.z + c1.w*iv1.w;
            float tB2 = c2.x*iv2.x + c2.y*iv2.y + c2.z*iv2.z + c2.w*iv2.w;
            float tB3 = c3.x*iv3.x + c3.y*iv3.y + c3.z*iv3.z + c3.w*iv3.w;
            s_part[w][4 * i + 1][lane] = (tB0 + tB1) + (tB2 + tB3);

            float tC0 = d0.x*iv0.x + d0.y*iv0.y + d0.z*iv0.z + d0.w*iv0.w;
            float tC1 = d1.x*iv1.x + d1.y*iv1.y + d1.z*iv1.z + d1.w*iv1.w;
            float tC2 = d2.x*iv2.x + d2.y*iv2.y + d2.z*iv2.z + d2.w*iv2.w;
            float tC3 = d3.x*iv3.x + d3.y*iv3.y + d3.z*iv3.z + d3.w*iv3.w;
            s_part[w][4 * i + 2][lane] = (tC0 + tC1) + (tC2 + tC3);

            float tD0 = e0.x*iv0.x + e0.y*iv0.y + e0.z*iv0.z + e0.w*iv0.w;
            float tD1 = e1.x*iv1.x + e1.y*iv1.y + e1.z*iv1.z + e1.w*iv1.w;
            float tD2 = e2.x*iv2.x + e2.y*iv2.y + e2.z*iv2.z + e2.w*iv2.w;
            float tD3 = e3.x*iv3.x + e3.y*iv3.y + e3.z*iv3.z + e3.w*iv3.w;
            s_part[w][4 * i + 3][lane] = (tD0 + tD1) + (tD2 + tD3);
        }
        __syncwarp();

        // Epilogue: lane l reduces row (rbase + l): 32 conflict-free LDS + bias.
        float acc = 0.0f;
        #pragma unroll
        for (int j = 0; j < 32; j++) acc += s_part[w][lane][j];
        const float hv = acc + b[rbase + lane];
        const float x2 = hv * hv;
        float runs = x2;
        float runp = 1.0f - x2;
        #pragma unroll
        for (int o = 16; o > 0; o >>= 1) {
            runs += __shfl_xor_sync(0xffffffffu, runs, o);
            runp *= __shfl_xor_sync(0xffffffffu, runp, o);
        }
        if (lane == 0) { s_rs[w] = runs; s_rp[w] = runp; }
        __syncthreads();

        // CTA partial -> cluster rank 0's smem slot for this rank.
        if (tid == 0) {
            float s = (s_rs[0] + s_rs[1]) + (s_rs[2] + s_rs[3]);
            float p = (s_rp[0] * s_rp[1]) * (s_rp[2] * s_rp[3]);
            float* dst = cluster.map_shared_rank(s_cl, 0);
            dst[rank * 2 + 0] = s;
            dst[rank * 2 + 1] = p;
        }
    } else {
        // y_out blocks: bx in [1024, 1028), 32 rows of Wy each, 8 rows per warp.
        const int rb = (bx - 1024) * 32 + w * 8;
        #pragma unroll
        for (int i = 0; i < 8; i += 2) {
            const int rowA = rb + i;
            const float4* WrA = (const float4*)(Wy + (size_t)rowA * TOTD);
            const float4* WrB = WrA + (TOTD / 4);
            float4 a0 = __ldg(WrA + lane +  0);
            float4 a1 = __ldg(WrA + lane + 32);
            float4 a2 = __ldg(WrA + lane + 64);
            float4 a3 = __ldg(WrA + lane + 96);
            float4 c0 = __ldg(WrB + lane +  0);
            float4 c1 = __ldg(WrB + lane + 32);
            float4 c2 = __ldg(WrB + lane + 64);
            float4 c3 = __ldg(WrB + lane + 96);

            float accA = a0.x*iv0.x + a0.y*iv0.y + a0.z*iv0.z + a0.w*iv0.w;
            float accB = c0.x*iv0.x + c0.y*iv0.y + c0.z*iv0.z + c0.w*iv0.w;
            accA      += a1.x*iv1.x + a1.y*iv1.y + a1.z*iv1.z + a1.w*iv1.w;
            accB      += c1.x*iv1.x + c1.y*iv1.y + c1.z*iv1.z + c1.w*iv1.w;
            accA      += a2.x*iv2.x + a2.y*iv2.y + a2.z*iv2.z + a2.w*iv2.w;
            accB      += c2.x*iv2.x + c2.y*iv2.y + c2.z*iv2.z + c2.w*iv2.w;
            accA      += a3.x*iv3.x + a3.y*iv3.y + a3.z*iv3.z + a3.w*iv3.w;
            accB      += c3.x*iv3.x + c3.y*iv3.y + c3.z*iv3.z + c3.w*iv3.w;

            #pragma unroll
            for (int o = 16; o > 0; o >>= 1) {
                accA += __shfl_xor_sync(0xffffffffu, accA, o);
                accB += __shfl_xor_sync(0xffffffffu, accB, o);
            }
            if (lane == 0) {
                out[HIDD + rowA]     = accA + by[rowA];
                out[HIDD + rowA + 1] = accB + by[rowA + 1];
            }
        }
    }

    // All CTAs of every cluster (incl. the y cluster) arrive here.
    cluster.sync();

    // Rank 0 of each hidden cluster combines the 4 quarter-partials -> out[kk].
    if (bx < 1024 && rank == 0 && tid == 0) {
        const int kk = bx >> 2;
        const float s = (s_cl[0] + s_cl[2]) + (s_cl[4] + s_cl[6]);
        float a;
        if (kk == 0) {
            a = expf(-0.5f * s);   // Gaussian scaling unit
        } else {
            const float p = (s_cl[1] * s_cl[3]) * (s_cl[5] * s_cl[7]);
            a = p * expf(-0.5f * s);   // Mexican-hat product
        }
        out[kk] = a;
    }
}

extern "C" void kernel_launch(void* const* d_in, const int* in_sizes, int n_in,
                              void* d_out, int out_size)
{
    const float* h  = (const float*)d_in[0];
    const float* y  = (const float*)d_in[1];
    const float* u  = (const float*)d_in[2];
    const float* W1 = (const float*)d_in[3];
    const float* b1 = (const float*)d_in[4];
    const float* W2 = (const float*)d_in[5];
    const float* b2 = (const float*)d_in[6];
    const float* Wy = (const float*)d_in[7];
    const float* by = (const float*)d_in[8];
    float* out = (float*)d_out;

    wavelet_cluster_kernel<<<1028, 128>>>(h, y, u, W1, b1, W2, b2, Wy, by, out);
}